// round 1
// baseline (speedup 1.0000x reference)
#include <cuda_runtime.h>

// DendriticLayer: B=512, N_IN=1024, N_OUT=256, T=100, dt=1
// CONN is block-diagonal: output o <- inputs [4o, 4o+4). Everything collapses
// to a per-(b,o) scalar recurrence + streaming softmax. One thread per (b,o).
//
// psp_j(t) = exp(-(t - s_j)/5) * [t >= s_j] = (w_j * exp(s_j/5)) * exp(-t/5) * [t >= s_j]
// I_t  = D_t * sum_{j active} c_j,  D_t = exp(-t/5) (running multiplier)
// v_t  = v_{t-1} + (I_t - v_{t-1}) * 0.1
// out  = sum_t t * exp(2 v_t) / sum_t exp(2 v_t)   (softmax w/o max-sub: x in [0,~9])

#define NSTEPS 100
#define NOUT   256

__global__ __launch_bounds__(256)
void dendritic_kernel(const float* __restrict__ spikes,  // [B, 1024]
                      const float* __restrict__ W,       // [256, 1024]
                      float* __restrict__ out)           // [B, 256]
{
    const int idx = blockIdx.x * blockDim.x + threadIdx.x;  // = b*256 + o
    const int o   = idx & (NOUT - 1);

    // spikes[b*1024 + 4o .. +3]  -> float4 index = idx  (16B aligned, coalesced)
    const float4 s4 = reinterpret_cast<const float4*>(spikes)[idx];
    // W[o*1024 + 4o .. +3]       -> float offset 1028*o = float4 index 257*o
    const float4 w4 = reinterpret_cast<const float4*>(W)[257 * o];

    const float inv_tau_syn = 0.2f;           // 1/5
    const float c0 = w4.x * __expf(s4.x * inv_tau_syn);
    const float c1 = w4.y * __expf(s4.y * inv_tau_syn);
    const float c2 = w4.z * __expf(s4.z * inv_tau_syn);
    const float c3 = w4.w * __expf(s4.w * inv_tau_syn);

    const float decay = 0.818730753077982f;   // exp(-0.2)
    const float a     = 0.1f;                 // dt/tau_mem
    const float K     = 2.0f;                 // 1/tau_soft

    float D  = 1.0f;    // exp(-t/5)
    float v  = 0.0f;
    float S  = 0.0f;
    float WS = 0.0f;
    float tf = 0.0f;

#pragma unroll 10
    for (int t = 0; t < NSTEPS; ++t) {
        float C = 0.0f;
        C += (tf >= s4.x) ? c0 : 0.0f;
        C += (tf >= s4.y) ? c1 : 0.0f;
        C += (tf >= s4.z) ? c2 : 0.0f;
        C += (tf >= s4.w) ? c3 : 0.0f;
        const float I = C * D;
        v = fmaf(I - v, a, v);                // v + (-v + I)*a  (matches reference order)
        const float e = __expf(v * K);        // FMUL + MUFU.EX2
        S  += e;
        WS  = fmaf(e, tf, WS);
        tf += 1.0f;
        D  *= decay;
    }

    out[idx] = WS / S;
}

extern "C" void kernel_launch(void* const* d_in, const int* in_sizes, int n_in,
                              void* d_out, int out_size)
{
    const float* spikes = (const float*)d_in[0];  // [512*1024]
    const float* W      = (const float*)d_in[1];  // [256*1024]
    float* out          = (float*)d_out;          // [512*256]

    dendritic_kernel<<<512, 256>>>(spikes, W, out);
}

// round 3
// speedup vs baseline: 1.5731x; 1.5731x over previous
#include <cuda_runtime.h>

// DendriticLayer: B=512, N_IN=1024, N_OUT=256, T=100, dt=1.
// CONN is block-diagonal (4 inputs per output) -> per-(b,o) scalar recurrence.
//
// psp_j(t) = exp(-(t-s_j)/5)[t>=s_j] = c_j * d^t * ind_j(t),  c_j = w_j exp(s_j/5), d = exp(-1/5)
// v_t = 0.9 v_{t-1} + 0.1 * d^t * sum_j c_j ind_j(t)
// Substitution u_t = v_t / d^t:   u_t = (0.9/d) u_{t-1} + 0.1 * sum_j c_j ind_j(t)
// exp(2 v_t) = exp2(u_t * E_t),   E_t = 2*log2(e)*d^t   (compile-time constant per step)
// ind_j(t) = saturate(t + (1 - ceil(s_j)))  -- exact for integer t
// out = (sum_t t*e_t) / (sum_t e_t)   (softmax needs no max-sub: arg in [0,~17])

#define NSTEPS 100

__device__ __forceinline__ float ex2(float x) {
    float y;
    asm("ex2.approx.ftz.f32 %0, %1;" : "=f"(y) : "f"(x));
    return y;
}

__host__ __device__ constexpr double cpow(double b, int n) {
    return n == 0 ? 1.0 : b * cpow(b, n - 1);
}

constexpr double D1 = 0.81873075307798185867;   // exp(-0.2)
constexpr double RD = 0.9 / D1;                 // (1-a)/d
constexpr double K2 = 2.8853900817779268147;    // 2*log2(e) = (1/tau_soft)*log2(e)

struct St {
    float q0, q1, q2, q3;     // 1 - ceil(s_j)
    float c0, c1, c2, c3;     // 0.1 * w_j * exp(s_j/5)
    float u, S, WS;
};

template <int T>
__device__ __forceinline__ void steps(St& st) {
    if constexpr (T < NSTEPS) {
        constexpr float tf  = (float)T;
        constexpr float Et  = (float)(K2 * cpow(D1, T));
        constexpr float rdf = (float)RD;

        // exact activation indicators (FADD.SAT with immediate)
        const float i0 = __saturatef(tf + st.q0);
        const float i1 = __saturatef(tf + st.q1);
        const float i2 = __saturatef(tf + st.q2);
        const float i3 = __saturatef(tf + st.q3);

        float Cp = i0 * st.c0;
        Cp = fmaf(i1, st.c1, Cp);
        Cp = fmaf(i2, st.c2, Cp);
        Cp = fmaf(i3, st.c3, Cp);

        st.u = fmaf(st.u, rdf, Cp);        // u_t = (0.9/d) u + 0.1*C_t
        const float e = ex2(st.u * Et);    // FMUL-imm + MUFU.EX2
        st.S += e;
        st.WS = fmaf(e, tf, st.WS);        // FFMA-imm

        steps<T + 1>(st);
    }
}

__global__ __launch_bounds__(128)
void dendritic_kernel(const float* __restrict__ spikes,  // [B,1024]
                      const float* __restrict__ W,       // [256,1024]
                      float* __restrict__ out)           // [B,256]
{
    const int idx = blockIdx.x * blockDim.x + threadIdx.x;  // b*256 + o
    const int o   = idx & 255;

    // spikes[b*1024 + 4o..4o+3] -> float4 index = idx (coalesced)
    const float4 s4 = reinterpret_cast<const float4*>(spikes)[idx];
    // W[o*1024 + 4o..4o+3] -> float offset 1028*o = float4 index 257*o
    const float4 w4 = reinterpret_cast<const float4*>(W)[257 * o];

    St st;
    st.q0 = 1.0f - ceilf(s4.x);
    st.q1 = 1.0f - ceilf(s4.y);
    st.q2 = 1.0f - ceilf(s4.z);
    st.q3 = 1.0f - ceilf(s4.w);
    st.c0 = 0.1f * w4.x * __expf(0.2f * s4.x);
    st.c1 = 0.1f * w4.y * __expf(0.2f * s4.y);
    st.c2 = 0.1f * w4.z * __expf(0.2f * s4.z);
    st.c3 = 0.1f * w4.w * __expf(0.2f * s4.w);
    st.u = 0.0f;
    st.S = 0.0f;
    st.WS = 0.0f;

    steps<0>(st);

    out[idx] = st.WS / st.S;
}

extern "C" void kernel_launch(void* const* d_in, const int* in_sizes, int n_in,
                              void* d_out, int out_size)
{
    const float* spikes = (const float*)d_in[0];  // [512*1024]
    const float* W      = (const float*)d_in[1];  // [256*1024]
    float* out          = (float*)d_out;          // [512*256]

    dendritic_kernel<<<1024, 128>>>(spikes, W, out);
}